// round 3
// baseline (speedup 1.0000x reference)
#include <cuda_runtime.h>
#include <mma.h>
#include <math.h>

using namespace nvcuda;

#define BB 64
#define LL 50
#define HH 1024
#define VV 50257

// ------------------------ scratch (no allocs allowed) ------------------------
__device__ float g_x[BB * HH];        // gathered embeddings
__device__ float g_q[BB * HH];        // query projection
__device__ float g_qk[BB * 2 * HH];   // key_w @ q
__device__ float g_wenc[BB * 2 * HH]; // attn-weighted encoder sum
__device__ float g_cprev[BB * HH];    // attention context (cell state)
__device__ float g_gates[BB * 4 * HH];
__device__ float g_hnext[BB * HH];

// ------------------------ embedding gather ------------------------
__global__ void k_gather(const int* __restrict__ idx, const float* __restrict__ emb) {
    int b = blockIdx.x;
    const float* src = emb + (size_t)idx[b] * HH;
    for (int j = threadIdx.x; j < HH; j += blockDim.x)
        g_x[b * HH + j] = src[j];
}

// ------------------------ generic M=64 tf32 GEMM ------------------------
// C[64, N] = concat_k( A1[64,K1] | A2[64,Ktot-K1] ) @ concat_k( B1 | B2 ) + bias1 + bias2
// B layout: if !B_NK, B is [K, N] row-major (ld = row stride). If B_NK, B is [N, K] row-major
// (i.e. we multiply by B^T). 256 threads, 8 warps in a 4(m) x 2(n) layout.
template <int BN, bool B_NK>
__global__ void gemm_tf32(const float* __restrict__ A1, const float* __restrict__ A2,
                          int K1, int Ktot,
                          const float* __restrict__ B1, const float* __restrict__ B2,
                          int ldb1, int ldb2,
                          const float* __restrict__ bias1, const float* __restrict__ bias2,
                          float* __restrict__ C, int ldc, int N) {
    constexpr int BNP = BN + 4;
    constexpr int TN  = BN / 32;                       // 16-wide n-subtiles per warp
    constexpr int ASZ = 64 * 36;
    constexpr int BSZ = B_NK ? (BN * 36) : (32 * BNP);
    constexpr int CSZ = 64 * BNP;

    struct ShAB { float A[ASZ]; float B[BSZ]; };
    union ShU { ShAB ab; float Cb[CSZ]; };
    __shared__ ShU sh;

    const int tid = threadIdx.x;
    const int w   = tid >> 5;
    const int wm  = w & 3;   // m tile: rows [wm*16, wm*16+16)
    const int wn  = w >> 2;  // n half: [wn*BN/2, ...)
    const int n0  = blockIdx.x * BN;

    wmma::fragment<wmma::matrix_a, 16, 16, 8, wmma::precision::tf32, wmma::row_major> fa;
    wmma::fragment<wmma::accumulator, 16, 16, 8, float> fc[TN];
#pragma unroll
    for (int t = 0; t < TN; t++) wmma::fill_fragment(fc[t], 0.f);

    for (int k0 = 0; k0 < Ktot; k0 += 32) {
        const float* Aseg; const float* Bseg; int lda, ldb, kk0;
        if (k0 < K1) { Aseg = A1; Bseg = B1; lda = K1;        ldb = ldb1; kk0 = k0; }
        else         { Aseg = A2; Bseg = B2; lda = Ktot - K1; ldb = ldb2; kk0 = k0 - K1; }

        __syncthreads();
        // A chunk: 64 x 32
#pragma unroll 4
        for (int i = tid; i < 64 * 32; i += 256) {
            int r = i >> 5, c = i & 31;
            sh.ab.A[r * 36 + c] = Aseg[(size_t)r * lda + kk0 + c];
        }
        if (!B_NK) {
            // B chunk: 32 x BN
#pragma unroll 4
            for (int i = tid; i < 32 * BN; i += 256) {
                int r = i / BN, c = i % BN;
                int n = n0 + c;
                sh.ab.B[r * BNP + c] = (n < N) ? Bseg[(size_t)(kk0 + r) * ldb + n] : 0.f;
            }
        } else {
            // B chunk: BN x 32 (rows are n)
#pragma unroll 4
            for (int i = tid; i < BN * 32; i += 256) {
                int r = i >> 5, c = i & 31;
                int n = n0 + r;
                sh.ab.B[r * 36 + c] = (n < N) ? Bseg[(size_t)n * ldb + kk0 + c] : 0.f;
            }
        }
        __syncthreads();

#pragma unroll
        for (int ks = 0; ks < 4; ks++) {
            wmma::load_matrix_sync(fa, &sh.ab.A[(wm * 16) * 36 + ks * 8], 36);
#pragma unroll
            for (int i = 0; i < fa.num_elements; i++) fa.x[i] = wmma::__float_to_tf32(fa.x[i]);
#pragma unroll
            for (int t = 0; t < TN; t++) {
                int ns = wn * (BN / 2) + t * 16;
                if (!B_NK) {
                    wmma::fragment<wmma::matrix_b, 16, 16, 8, wmma::precision::tf32, wmma::row_major> fb;
                    wmma::load_matrix_sync(fb, &sh.ab.B[(ks * 8) * BNP + ns], BNP);
#pragma unroll
                    for (int i = 0; i < fb.num_elements; i++) fb.x[i] = wmma::__float_to_tf32(fb.x[i]);
                    wmma::mma_sync(fc[t], fa, fb, fc[t]);
                } else {
                    wmma::fragment<wmma::matrix_b, 16, 16, 8, wmma::precision::tf32, wmma::col_major> fb;
                    wmma::load_matrix_sync(fb, &sh.ab.B[ns * 36 + ks * 8], 36);
#pragma unroll
                    for (int i = 0; i < fb.num_elements; i++) fb.x[i] = wmma::__float_to_tf32(fb.x[i]);
                    wmma::mma_sync(fc[t], fa, fb, fc[t]);
                }
            }
        }
    }

    __syncthreads();
#pragma unroll
    for (int t = 0; t < TN; t++) {
        int ns = wn * (BN / 2) + t * 16;
        wmma::store_matrix_sync(&sh.Cb[(wm * 16) * BNP + ns], fc[t], BNP, wmma::mem_row_major);
    }
    __syncthreads();

    for (int i = tid; i < 64 * BN; i += 256) {
        int r = i / BN, c = i % BN;
        int n = n0 + c;
        if (n < N) {
            float v = sh.Cb[r * BNP + c];
            if (bias1) v += bias1[n];
            if (bias2) v += bias2[n];
            C[(size_t)r * ldc + n] = v;
        }
    }
}

// ------------------------ attention: scores -> softmax -> weighted enc sum ------------------------
__global__ void k_attn(const float* __restrict__ enc, const float* __restrict__ key_b,
                       float* __restrict__ out_attn) {
    int b = blockIdx.x;
    int tid = threadIdx.x;  // 256
    __shared__ float s_sc[LL];
    __shared__ float red[256];
    __shared__ float s_qkb;

    // qkb = q[b] . key_b
    float p = 0.f;
    for (int j = tid; j < HH; j += 256) p += g_q[b * HH + j] * key_b[j];
    red[tid] = p; __syncthreads();
    for (int s = 128; s > 0; s >>= 1) { if (tid < s) red[tid] += red[tid + s]; __syncthreads(); }
    if (tid == 0) s_qkb = red[0];
    __syncthreads();

    // scores: one warp per l (strided)
    int w = tid >> 5, lane = tid & 31;
    const float* qk = g_qk + b * 2 * HH;
    for (int l = w; l < LL; l += 8) {
        const float* e = enc + ((size_t)b * LL + l) * 2 * HH;
        float acc = 0.f;
        for (int j = lane; j < 2 * HH; j += 32) acc += e[j] * qk[j];
#pragma unroll
        for (int o = 16; o > 0; o >>= 1) acc += __shfl_xor_sync(0xffffffffu, acc, o);
        if (lane == 0) s_sc[l] = (acc + s_qkb) * (1.f / HH);
    }
    __syncthreads();

    // softmax over L=50 (serial on thread 0; trivial)
    if (tid == 0) {
        float m = -1e30f;
        for (int l = 0; l < LL; l++) m = fmaxf(m, s_sc[l]);
        float s = 0.f;
        for (int l = 0; l < LL; l++) { float e = expf(s_sc[l] - m); s_sc[l] = e; s += e; }
        float inv = 1.f / s;
        for (int l = 0; l < LL; l++) s_sc[l] *= inv;
    }
    __syncthreads();

    if (out_attn)
        for (int l = tid; l < LL; l += 256) out_attn[b * LL + l] = s_sc[l];

    // wenc[b, j] = sum_l attn_l * enc[b, l, j]
    for (int j = tid; j < 2 * HH; j += 256) {
        float acc = 0.f;
#pragma unroll 5
        for (int l = 0; l < LL; l++) acc += s_sc[l] * enc[((size_t)b * LL + l) * 2 * HH + j];
        g_wenc[b * 2 * HH + j] = acc;
    }
}

// ------------------------ LSTM elementwise ------------------------
__global__ void k_lstm(float* __restrict__ out_h) {
    int b = blockIdx.x;
    const float* g = g_gates + b * 4 * HH;
    for (int h = threadIdx.x; h < HH; h += blockDim.x) {
        float f  = 1.f / (1.f + expf(-g[h]));
        float ig = 1.f / (1.f + expf(-g[HH + h]));
        float cb = tanhf(g[2 * HH + h]);
        float o  = 1.f / (1.f + expf(-g[3 * HH + h]));
        float c  = f * g_cprev[b * HH + h] + ig * cb;
        float hn = o * tanhf(c);
        g_hnext[b * HH + h] = hn;
        if (out_h) out_h[b * HH + h] = hn;
    }
}

// ------------------------ in-place log-softmax over V ------------------------
__global__ void k_logsoftmax(float* __restrict__ logits) {
    int b = blockIdx.x;
    float* row = logits + (size_t)b * VV;
    __shared__ float red[512];
    int tid = threadIdx.x;

    float m = -1e30f;
    for (int v = tid; v < VV; v += 512) m = fmaxf(m, row[v]);
    red[tid] = m; __syncthreads();
    for (int s = 256; s > 0; s >>= 1) { if (tid < s) red[tid] = fmaxf(red[tid], red[tid + s]); __syncthreads(); }
    m = red[0];
    __syncthreads();

    float sum = 0.f;
    for (int v = tid; v < VV; v += 512) sum += expf(row[v] - m);
    red[tid] = sum; __syncthreads();
    for (int s = 256; s > 0; s >>= 1) { if (tid < s) red[tid] += red[tid + s]; __syncthreads(); }
    float lse = m + logf(red[0]);

    for (int v = tid; v < VV; v += 512) row[v] -= lse;
}

// ------------------------ launch ------------------------
extern "C" void kernel_launch(void* const* d_in, const int* in_sizes, int n_in,
                              void* d_out, int out_size) {
    (void)in_sizes; (void)n_in;
    const int*   idx     = (const int*)  d_in[0];
    const float* h_prev  = (const float*)d_in[1];
    const float* enc     = (const float*)d_in[2];
    const float* emb     = (const float*)d_in[3];
    const float* w_x     = (const float*)d_in[4];
    const float* b_x     = (const float*)d_in[5];
    const float* w_h     = (const float*)d_in[6];
    const float* b_h     = (const float*)d_in[7];
    const float* key_w   = (const float*)d_in[8];
    const float* key_b   = (const float*)d_in[9];
    const float* value_w = (const float*)d_in[10];
    const float* value_b = (const float*)d_in[11];
    const float* query_w = (const float*)d_in[12];
    const float* query_b = (const float*)d_in[13];
    const float* out_w   = (const float*)d_in[14];
    const float* out_b   = (const float*)d_in[15];

    float* out      = (float*)d_out;
    float* out_logp = out;
    float* out_h    = nullptr;
    float* out_attn = nullptr;
    long long need = (long long)BB * VV + (long long)BB * HH + (long long)BB * LL;
    if ((long long)out_size >= need) {
        out_h    = out + (size_t)BB * VV;
        out_attn = out_h + (size_t)BB * HH;
    }

    float *p_x, *p_q, *p_qk, *p_wenc, *p_cprev, *p_gates, *p_hnext;
    cudaGetSymbolAddress((void**)&p_x,     g_x);
    cudaGetSymbolAddress((void**)&p_q,     g_q);
    cudaGetSymbolAddress((void**)&p_qk,    g_qk);
    cudaGetSymbolAddress((void**)&p_wenc,  g_wenc);
    cudaGetSymbolAddress((void**)&p_cprev, g_cprev);
    cudaGetSymbolAddress((void**)&p_gates, g_gates);
    cudaGetSymbolAddress((void**)&p_hnext, g_hnext);

    // independent front-end work
    k_gather<<<BB, 256>>>(idx, emb);

    // q = h_prev @ query_w + query_b            [64,1024]
    gemm_tf32<32, false><<<HH / 32, 256>>>(h_prev, h_prev, HH, HH,
                                           query_w, query_w, HH, HH,
                                           query_b, nullptr, p_q, HH, HH);
    // qk = q @ key_w^T                          [64,2048]
    gemm_tf32<32, true><<<(2 * HH) / 32, 256>>>(p_q, p_q, HH, HH,
                                                key_w, key_w, HH, HH,
                                                nullptr, nullptr, p_qk, 2 * HH, 2 * HH);
    // scores -> softmax -> wenc (+ attn output) [64,2048]
    k_attn<<<BB, 256>>>(enc, key_b, out_attn);

    // c_prev = wenc @ value_w + value_b         [64,1024]
    gemm_tf32<32, false><<<HH / 32, 256>>>(p_wenc, p_wenc, 2 * HH, 2 * HH,
                                           value_w, value_w, HH, HH,
                                           value_b, nullptr, p_cprev, HH, HH);
    // gates = x @ w_x + h_prev @ w_h + b_x + b_h [64,4096]  (concat-K GEMM)
    gemm_tf32<32, false><<<(4 * HH) / 32, 256>>>(p_x, h_prev, HH, 2 * HH,
                                                 w_x, w_h, 4 * HH, 4 * HH,
                                                 b_x, b_h, p_gates, 4 * HH, 4 * HH);
    // LSTM elementwise -> h_next (+ output)
    k_lstm<<<BB, 256>>>(out_h);

    // logits = h_next @ out_w + out_b           [64,50257]  (the big one)
    gemm_tf32<128, false><<<(VV + 127) / 128, 256>>>(p_hnext, p_hnext, HH, HH,
                                                     out_w, out_w, VV, VV,
                                                     out_b, nullptr, out_logp, VV, VV);
    // in-place log-softmax
    k_logsoftmax<<<BB, 512>>>(out_logp);
}

// round 5
// speedup vs baseline: 1.9951x; 1.9951x over previous
#include <cuda_runtime.h>
#include <mma.h>
#include <math.h>

using namespace nvcuda;

#define BB 64
#define LL 50
#define HH 1024
#define VV 50257

// ------------------------ scratch (16B aligned for float4/cp.async) ------------------------
__device__ __align__(16) float g_x[BB * HH];
__device__ __align__(16) float g_q[BB * HH];
__device__ __align__(16) float g_qk[BB * 2 * HH];
__device__ __align__(16) float g_scores[BB * LL];
__device__ __align__(16) float g_attn[BB * LL];
__device__ __align__(16) float g_wenc[BB * 2 * HH];
__device__ __align__(16) float g_cprev[BB * HH];
__device__ __align__(16) float g_gates[BB * 4 * HH];
__device__ __align__(16) float g_hnext[BB * HH];
__device__ __align__(16) float g_lse[BB * 8 * 2];

// ------------------------ cp.async helpers ------------------------
__device__ __forceinline__ unsigned smem_u32(const void* p) {
    return (unsigned)__cvta_generic_to_shared(p);
}
__device__ __forceinline__ void cp16(unsigned dst, const void* src) {
    asm volatile("cp.async.cg.shared.global [%0], [%1], 16;\n" :: "r"(dst), "l"(src));
}
__device__ __forceinline__ void cp4(unsigned dst, const void* src, int sz) {
    asm volatile("cp.async.ca.shared.global [%0], [%1], 4, %2;\n" :: "r"(dst), "l"(src), "r"(sz));
}
__device__ __forceinline__ void cp_commit() { asm volatile("cp.async.commit_group;\n"); }
template <int N> __device__ __forceinline__ void cp_wait() {
    asm volatile("cp.async.wait_group %0;\n" :: "n"(N));
}

// ------------------------ embedding gather ------------------------
__global__ void __launch_bounds__(256) k_gather(const int* __restrict__ idx,
                                                const float* __restrict__ emb) {
    int b = blockIdx.x;
    const float4* src = (const float4*)(emb + (size_t)idx[b] * HH);
    float4* dst = (float4*)(g_x + b * HH);
    if (threadIdx.x < HH / 4) dst[threadIdx.x] = src[threadIdx.x];
}

// ------------------------ q bias add ------------------------
__global__ void __launch_bounds__(256) k_qbias(const float* __restrict__ query_b) {
    int b = blockIdx.x;
    for (int j = threadIdx.x; j < HH; j += 256) g_q[b * HH + j] += query_b[j];
}

// ------------------------ pipelined M=64 tf32 GEMM (no bias) ------------------------
// C[64,N] = [A1 | A2] @ [B1 ; B2].  B row-major [K,N] (ldb = row stride) if !B_NK,
// else B is [N,K] row-major (multiply by B^T). BK=16, S-stage cp.async pipeline.
// ALL wmma ldm values are multiples of 4 floats (16B) — hard requirement.
template <int BN, int S, bool B_NK>
__global__ void __launch_bounds__(256) gemm_pipe(
    const float* __restrict__ A1, const float* __restrict__ A2, int K1, int Ktot,
    const float* __restrict__ B1, const float* __restrict__ B2, int ldb1, int ldb2,
    float* __restrict__ C, int ldc, int N) {
    constexpr int BK  = 16;
    constexpr int AP  = 20;                 // A row stride (mult of 4)
    constexpr int BPL = BN + 4;             // KN-layout row stride (mult of 4)
    constexpr int BNS = 20;                 // NK-layout row stride (mult of 4)
    constexpr int BSTG = B_NK ? (BN * BNS) : (BK * BPL);
    constexpr int TN = BN / 32;
    constexpr int PP = 20;                  // patch stride (mult of 4)

    __shared__ float sA[S][64 * AP];
    __shared__ float sB[S][BSTG];

    const int tid = threadIdx.x, w = tid >> 5, lane = tid & 31;
    const int wm = w & 3, wn = w >> 2;
    const int n0 = blockIdx.x * BN;
    const int T = Ktot / BK;
    const bool fullN = (n0 + BN) <= N;

    auto issue = [&](int t) {
        int k0 = t * BK;
        const float* Aseg; const float* Bseg; int lda, ldb, kk;
        if (k0 < K1) { Aseg = A1; Bseg = B1; lda = K1;        ldb = ldb1; kk = k0; }
        else         { Aseg = A2; Bseg = B2; lda = Ktot - K1; ldb = ldb2; kk = k0 - K1; }
        int buf = t % S;
        // A: 64x16 floats, one float4 per thread
        int ar = tid >> 2, av = (tid & 3) * 4;
        cp16(smem_u32(&sA[buf][ar * AP + av]), Aseg + (size_t)ar * lda + kk + av);
        // B
        constexpr int CNT = BK * BN / 256;
        if (!B_NK) {
#pragma unroll
            for (int i = 0; i < CNT; i++) {
                int idx = tid + i * 256, r = idx / BN, c = idx % BN;
                int n = n0 + c;
                int ok = (fullN || n < N);
                const float* src = Bseg + (size_t)(kk + r) * ldb + (ok ? n : 0);
                cp4(smem_u32(&sB[buf][r * BPL + c]), src, ok ? 4 : 0);
            }
        } else {
#pragma unroll
            for (int i = 0; i < CNT; i++) {
                int idx = tid + i * 256, r = idx >> 4, c = idx & 15;
                int n = n0 + r;
                int ok = (fullN || n < N);
                const float* src = Bseg + (size_t)(ok ? n : 0) * ldb + kk + c;
                cp4(smem_u32(&sB[buf][r * BNS + c]), src, ok ? 4 : 0);
            }
        }
    };

    wmma::fragment<wmma::matrix_a, 16, 16, 8, wmma::precision::tf32, wmma::row_major> fa;
    wmma::fragment<wmma::accumulator, 16, 16, 8, float> fc[TN];
#pragma unroll
    for (int t = 0; t < TN; t++) wmma::fill_fragment(fc[t], 0.f);

    // prologue: prefetch S-1 stages
#pragma unroll
    for (int p = 0; p < S - 1; p++) { if (p < T) issue(p); cp_commit(); }

    for (int t = 0; t < T; t++) {
        cp_wait<S - 2>();
        __syncthreads();
        int buf = t % S;
#pragma unroll
        for (int ks = 0; ks < 2; ks++) {
            wmma::load_matrix_sync(fa, &sA[buf][wm * 16 * AP + ks * 8], AP);
#pragma unroll
            for (int i = 0; i < fa.num_elements; i++) fa.x[i] = wmma::__float_to_tf32(fa.x[i]);
#pragma unroll
            for (int tt = 0; tt < TN; tt++) {
                int ns = wn * (BN / 2) + tt * 16;
                if (!B_NK) {
                    wmma::fragment<wmma::matrix_b, 16, 16, 8, wmma::precision::tf32, wmma::row_major> fb;
                    wmma::load_matrix_sync(fb, &sB[buf][ks * 8 * BPL + ns], BPL);
#pragma unroll
                    for (int i = 0; i < fb.num_elements; i++) fb.x[i] = wmma::__float_to_tf32(fb.x[i]);
                    wmma::mma_sync(fc[tt], fa, fb, fc[tt]);
                } else {
                    wmma::fragment<wmma::matrix_b, 16, 16, 8, wmma::precision::tf32, wmma::col_major> fb;
                    wmma::load_matrix_sync(fb, &sB[buf][ns * BNS + ks * 8], BNS);
#pragma unroll
                    for (int i = 0; i < fb.num_elements; i++) fb.x[i] = wmma::__float_to_tf32(fb.x[i]);
                    wmma::mma_sync(fc[tt], fa, fb, fc[tt]);
                }
            }
        }
        __syncthreads();
        if (t + S - 1 < T) issue(t + S - 1);
        cp_commit();
    }

    __syncthreads();
    // epilogue: direct global stores only when ldc is 16B-aligned and tile is full;
    // otherwise stage through per-warp smem patch (ldm = PP, mult of 4) + scalar stores.
    float* patch = &sA[0][0] + w * (16 * PP);
    const bool ldc_ok = (ldc & 3) == 0;
#pragma unroll
    for (int tt = 0; tt < TN; tt++) {
        int nc = n0 + wn * (BN / 2) + tt * 16;
        int r0 = wm * 16;
        if (nc >= N) continue;
        if (ldc_ok && nc + 16 <= N) {
            wmma::store_matrix_sync(&C[(size_t)r0 * ldc + nc], fc[tt], ldc, wmma::mem_row_major);
        } else {
            wmma::store_matrix_sync(patch, fc[tt], PP, wmma::mem_row_major);
            __syncwarp();
            for (int i = lane; i < 256; i += 32) {
                int r = i >> 4, c = i & 15;
                if (nc + c < N) C[(size_t)(r0 + r) * ldc + nc + c] = patch[r * PP + c];
            }
            __syncwarp();
        }
    }
}

// ------------------------ attention scores: scores[b,l] = enc[b,l]·qk[b] / H ------------------------
__global__ void __launch_bounds__(256) k_scores(const float* __restrict__ enc) {
    int b = blockIdx.x;
    int tid = threadIdx.x, w = tid >> 5, lane = tid & 31;
    __shared__ __align__(16) float sq[2 * HH];
    const float4* qk4 = (const float4*)(g_qk + b * 2 * HH);
    for (int i = tid; i < 2 * HH / 4; i += 256) ((float4*)sq)[i] = qk4[i];
    __syncthreads();

    for (int ll = w; ll < 10; ll += 8) {
        int l = blockIdx.y * 10 + ll;
        const float* e = enc + ((size_t)b * LL + l) * 2 * HH;
        float acc = 0.f;
        for (int j = lane * 4; j < 2 * HH; j += 128) {
            float4 ev = *(const float4*)(e + j);
            float4 qv = *(const float4*)(sq + j);
            acc += ev.x * qv.x + ev.y * qv.y + ev.z * qv.z + ev.w * qv.w;
        }
#pragma unroll
        for (int o = 16; o > 0; o >>= 1) acc += __shfl_xor_sync(0xffffffffu, acc, o);
        if (lane == 0) g_scores[b * LL + l] = acc * (1.f / HH);
    }
}

// ------------------------ softmax over L=50 (one warp per row) ------------------------
__global__ void __launch_bounds__(32) k_softmax(float* __restrict__ out_attn) {
    int b = blockIdx.x, t = threadIdx.x;
    float v0 = (t < LL) ? g_scores[b * LL + t] : -1e30f;
    float v1 = (t + 32 < LL) ? g_scores[b * LL + t + 32] : -1e30f;
    float m = fmaxf(v0, v1);
#pragma unroll
    for (int o = 16; o > 0; o >>= 1) m = fmaxf(m, __shfl_xor_sync(0xffffffffu, m, o));
    float e0 = (t < LL) ? expf(v0 - m) : 0.f;
    float e1 = (t + 32 < LL) ? expf(v1 - m) : 0.f;
    float s = e0 + e1;
#pragma unroll
    for (int o = 16; o > 0; o >>= 1) s += __shfl_xor_sync(0xffffffffu, s, o);
    float inv = 1.f / s;
    if (t < LL)      { g_attn[b * LL + t] = e0 * inv;      if (out_attn) out_attn[b * LL + t] = e0 * inv; }
    if (t + 32 < LL) { g_attn[b * LL + t + 32] = e1 * inv; if (out_attn) out_attn[b * LL + t + 32] = e1 * inv; }
}

// ------------------------ weighted encoder sum: wenc[b,j] = sum_l attn[l]*enc[b,l,j] ------------------------
__global__ void __launch_bounds__(256) k_wenc(const float* __restrict__ enc) {
    int b = blockIdx.x;
    int j = blockIdx.y * 256 + threadIdx.x;
    __shared__ float at[LL];
    if (threadIdx.x < LL) at[threadIdx.x] = g_attn[b * LL + threadIdx.x];
    __syncthreads();
    const float* e = enc + (size_t)b * LL * 2 * HH + j;
    float acc = 0.f;
#pragma unroll 5
    for (int l = 0; l < LL; l++) acc += at[l] * e[(size_t)l * 2 * HH];
    g_wenc[b * 2 * HH + j] = acc;
}

// ------------------------ LSTM elementwise (folds value_b, b_x, b_h) ------------------------
__global__ void __launch_bounds__(256) k_lstm(const float* __restrict__ value_b,
                                              const float* __restrict__ b_x,
                                              const float* __restrict__ b_h,
                                              float* __restrict__ out_h) {
    int b = blockIdx.x;
    const float* g = g_gates + b * 4 * HH;
    for (int h = threadIdx.x; h < HH; h += 256) {
        float bf = b_x[h] + b_h[h];
        float bi = b_x[HH + h] + b_h[HH + h];
        float bc = b_x[2 * HH + h] + b_h[2 * HH + h];
        float bo = b_x[3 * HH + h] + b_h[3 * HH + h];
        float f  = 1.f / (1.f + expf(-(g[h] + bf)));
        float ig = 1.f / (1.f + expf(-(g[HH + h] + bi)));
        float cb = tanhf(g[2 * HH + h] + bc);
        float o  = 1.f / (1.f + expf(-(g[3 * HH + h] + bo)));
        float cp = g_cprev[b * HH + h] + value_b[h];
        float c  = f * cp + ig * cb;
        float hn = o * tanhf(c);
        g_hnext[b * HH + h] = hn;
        if (out_h) out_h[b * HH + h] = hn;
    }
}

// ------------------------ log-softmax: pass1 partial (m, sumexp), pass2 apply ------------------------
#define LSM_CH 6283
__global__ void __launch_bounds__(256) k_lsm1(const float* __restrict__ logits,
                                              const float* __restrict__ out_b) {
    int b = blockIdx.x, c = blockIdx.y, tid = threadIdx.x;
    int start = c * LSM_CH, end = min(start + LSM_CH, VV);
    const float* row = logits + (size_t)b * VV;
    __shared__ float red[256];
    float m = -1e30f;
    for (int v = start + tid; v < end; v += 256) m = fmaxf(m, row[v] + out_b[v]);
    red[tid] = m; __syncthreads();
    for (int s = 128; s > 0; s >>= 1) { if (tid < s) red[tid] = fmaxf(red[tid], red[tid + s]); __syncthreads(); }
    m = red[0]; __syncthreads();
    float sum = 0.f;
    for (int v = start + tid; v < end; v += 256) sum += __expf(row[v] + out_b[v] - m);
    red[tid] = sum; __syncthreads();
    for (int s = 128; s > 0; s >>= 1) { if (tid < s) red[tid] += red[tid + s]; __syncthreads(); }
    if (tid == 0) { g_lse[(b * 8 + c) * 2] = m; g_lse[(b * 8 + c) * 2 + 1] = red[0]; }
}

__global__ void __launch_bounds__(256) k_lsm2(float* __restrict__ logits,
                                              const float* __restrict__ out_b) {
    int b = blockIdx.x, c = blockIdx.y, tid = threadIdx.x;
    float M = -1e30f;
#pragma unroll
    for (int i = 0; i < 8; i++) M = fmaxf(M, g_lse[(b * 8 + i) * 2]);
    float S = 0.f;
#pragma unroll
    for (int i = 0; i < 8; i++) S += g_lse[(b * 8 + i) * 2 + 1] * __expf(g_lse[(b * 8 + i) * 2] - M);
    float lse = M + logf(S);
    int start = c * LSM_CH, end = min(start + LSM_CH, VV);
    float* row = logits + (size_t)b * VV;
    for (int v = start + tid; v < end; v += 256) row[v] = row[v] + out_b[v] - lse;
}

// ------------------------ launch ------------------------
extern "C" void kernel_launch(void* const* d_in, const int* in_sizes, int n_in,
                              void* d_out, int out_size) {
    (void)in_sizes; (void)n_in;
    const int*   idx     = (const int*)  d_in[0];
    const float* h_prev  = (const float*)d_in[1];
    const float* enc     = (const float*)d_in[2];
    const float* emb     = (const float*)d_in[3];
    const float* w_x     = (const float*)d_in[4];
    const float* b_x     = (const float*)d_in[5];
    const float* w_h     = (const float*)d_in[6];
    const float* b_h     = (const float*)d_in[7];
    const float* key_w   = (const float*)d_in[8];
    const float* value_w = (const float*)d_in[10];
    const float* value_b = (const float*)d_in[11];
    const float* query_w = (const float*)d_in[12];
    const float* query_b = (const float*)d_in[13];
    const float* out_w   = (const float*)d_in[14];
    const float* out_b   = (const float*)d_in[15];
    // d_in[9] = key_b: dropped — softmax is shift-invariant in the constant q·key_b.

    float* out      = (float*)d_out;
    float* out_logp = out;
    float* out_h    = nullptr;
    float* out_attn = nullptr;
    long long need = (long long)BB * VV + (long long)BB * HH + (long long)BB * LL;
    if ((long long)out_size >= need) {
        out_h    = out + (size_t)BB * VV;
        out_attn = out_h + (size_t)BB * HH;
    }

    float *p_x, *p_q, *p_qk, *p_wenc, *p_cprev, *p_gates, *p_hnext;
    cudaGetSymbolAddress((void**)&p_x,     g_x);
    cudaGetSymbolAddress((void**)&p_q,     g_q);
    cudaGetSymbolAddress((void**)&p_qk,    g_qk);
    cudaGetSymbolAddress((void**)&p_wenc,  g_wenc);
    cudaGetSymbolAddress((void**)&p_cprev, g_cprev);
    cudaGetSymbolAddress((void**)&p_gates, g_gates);
    cudaGetSymbolAddress((void**)&p_hnext, g_hnext);

    k_gather<<<BB, 256>>>(idx, emb);

    // q = h_prev @ query_w (+ query_b via k_qbias)         [64,1024]
    gemm_pipe<64, 5, false><<<HH / 64, 256>>>(h_prev, h_prev, HH, HH,
                                              query_w, query_w, HH, HH, p_q, HH, HH);
    k_qbias<<<BB, 256>>>(query_b);

    // qk = q @ key_w^T                                     [64,2048]
    gemm_pipe<64, 4, true><<<(2 * HH) / 64, 256>>>(p_q, p_q, HH, HH,
                                                   key_w, key_w, HH, HH, p_qk, 2 * HH, 2 * HH);
    // scores -> softmax -> weighted enc sum
    k_scores<<<dim3(BB, 5), 256>>>(enc);
    k_softmax<<<BB, 32>>>(out_attn);
    k_wenc<<<dim3(BB, 8), 256>>>(enc);

    // c_prev = wenc @ value_w (value_b folded into k_lstm) [64,1024]
    gemm_pipe<64, 5, false><<<HH / 64, 256>>>(p_wenc, p_wenc, 2 * HH, 2 * HH,
                                              value_w, value_w, HH, HH, p_cprev, HH, HH);
    // gates = x @ w_x + h_prev @ w_h (biases in k_lstm)    [64,4096]
    gemm_pipe<64, 5, false><<<(4 * HH) / 64, 256>>>(p_x, h_prev, HH, 2 * HH,
                                                    w_x, w_h, 4 * HH, 4 * HH, p_gates, 4 * HH, 4 * HH);
    k_lstm<<<BB, 256>>>(value_b, b_x, b_h, out_h);

    // logits = h_next @ out_w (out_b folded into log-softmax)  [64,50257]
    gemm_pipe<128, 3, false><<<(VV + 127) / 128, 256>>>(p_hnext, p_hnext, HH, HH,
                                                        out_w, out_w, VV, VV, out_logp, VV, VV);
    k_lsm1<<<dim3(BB, 8), 256>>>(out_logp, out_b);
    k_lsm2<<<dim3(BB, 8), 256>>>(out_logp, out_b);
}

// round 7
// speedup vs baseline: 3.3623x; 1.6853x over previous
#include <cuda_runtime.h>
#include <mma.h>
#include <math.h>

using namespace nvcuda;

#define BB 64
#define LL 50
#define HH 1024
#define VV 50257

// ------------------------ scratch ------------------------
__device__ __align__(16) float g_x[BB * HH];
__device__ __align__(16) float g_q[BB * HH];
__device__ __align__(16) float g_scores[BB * LL];
__device__ __align__(16) float g_attn[BB * LL];
__device__ __align__(16) float g_wenc[BB * 2 * HH];
__device__ __align__(16) float g_hnext[BB * HH];
__device__ __align__(16) float g_lse[BB * 8 * 2];
// split-K partials
__device__ __align__(16) float g_partq[4 * BB * HH];
__device__ __align__(16) float g_partqk[4 * BB * 2 * HH];
__device__ __align__(16) float g_partc[8 * BB * HH];
__device__ __align__(16) float g_partg[8 * BB * 4 * HH];

// ------------------------ cp.async helpers ------------------------
__device__ __forceinline__ unsigned smem_u32(const void* p) {
    return (unsigned)__cvta_generic_to_shared(p);
}
__device__ __forceinline__ void cp16(unsigned dst, const void* src) {
    asm volatile("cp.async.cg.shared.global [%0], [%1], 16;\n" :: "r"(dst), "l"(src));
}
__device__ __forceinline__ void cp4(unsigned dst, const void* src, int sz) {
    asm volatile("cp.async.ca.shared.global [%0], [%1], 4, %2;\n" :: "r"(dst), "l"(src), "r"(sz));
}
__device__ __forceinline__ void cp_commit() { asm volatile("cp.async.commit_group;\n"); }
template <int N> __device__ __forceinline__ void cp_wait() {
    asm volatile("cp.async.wait_group %0;\n" :: "n"(N));
}

// ------------------------ embedding gather ------------------------
__global__ void __launch_bounds__(256) k_gather(const int* __restrict__ idx,
                                                const float* __restrict__ emb) {
    int b = blockIdx.x;
    const float4* src = (const float4*)(emb + (size_t)idx[b] * HH);
    float4* dst = (float4*)(g_x + b * HH);
    if (threadIdx.x < HH / 4) dst[threadIdx.x] = src[threadIdx.x];
}

// ------------------------ q = sum(parts) + bias ------------------------
__global__ void __launch_bounds__(256) k_qbias(const float* __restrict__ query_b) {
    int b = blockIdx.x;
    int j = blockIdx.y * 256 + threadIdx.x;
    float s = query_b[j];
#pragma unroll
    for (int p = 0; p < 4; p++) s += g_partq[p * BB * HH + b * HH + j];
    g_q[b * HH + j] = s;
}

// ------------------------ pipelined M=64 tf32 GEMM with optional split-K ------------------------
// C[64,N] = [A1 | A2] @ [B1 ; B2].  !B_NK: B row-major [K,N]; B_NK: B is [N,K] (B^T mult).
// gridDim.y = KS splits; split ky writes partials to C + ky*64*ldc.
// B fills use 16B cp.async when ldb % 4 == 0, else coalesced 4B cp.async (odd-ldb out_w).
template <int BN, int S, bool B_NK>
__global__ void __launch_bounds__(256) gemm_pipe(
    const float* __restrict__ A1, const float* __restrict__ A2, int K1, int Ktot,
    const float* __restrict__ B1, const float* __restrict__ B2, int ldb1, int ldb2,
    float* __restrict__ C, int ldc, int N) {
    constexpr int BK  = 16;
    constexpr int AP  = 20;
    constexpr int BPL = BN + 4;     // KN row stride
    constexpr int BNS = 20;         // NK row stride
    constexpr int BSTG = B_NK ? (BN * BNS) : (BK * BPL);
    constexpr int TN = BN / 32;

    extern __shared__ char dsm[];
    float* sA = (float*)dsm;
    float* sB = (float*)(dsm + (size_t)S * 64 * AP * 4);

    const int tid = threadIdx.x, w = tid >> 5;
    const int wm = w & 3, wn = w >> 2;
    const int n0 = blockIdx.x * BN;
    const int Tall = Ktot / BK;
    const int Tper = Tall / gridDim.y;
    const int t0 = blockIdx.y * Tper;
    const bool fullN = (n0 + BN) <= N;
    const bool bAligned = (((ldb1 | ldb2) & 3) == 0);
    C += (size_t)blockIdx.y * 64 * ldc;

    auto issue = [&](int t) {
        int k0 = t * BK;
        const float* Aseg; const float* Bseg; int lda, ldb, kk;
        if (k0 < K1) { Aseg = A1; Bseg = B1; lda = K1;        ldb = ldb1; kk = k0; }
        else         { Aseg = A2; Bseg = B2; lda = Ktot - K1; ldb = ldb2; kk = k0 - K1; }
        int buf = (t - t0) % S;
        // A: 64x16 floats = 256 float4, one per thread (always 16B-aligned)
        int ar = tid >> 2, av = (tid & 3) * 4;
        cp16(smem_u32(&sA[buf * 64 * AP + ar * AP + av]), Aseg + (size_t)ar * lda + kk + av);
        float* sBb = &sB[buf * BSTG];
        if (!B_NK) {
            if (bAligned) {
                constexpr int NV = BN / 4;
                constexpr int TOT = BK * NV;
#pragma unroll
                for (int i = tid; i < TOT; i += 256) {
                    int r = i / NV, c = (i % NV) * 4;
                    cp16(smem_u32(&sBb[r * BPL + c]), Bseg + (size_t)(kk + r) * ldb + n0 + c);
                }
            } else {
                // odd ldb (out_w): coalesced 4B cp.async, zfill out-of-range
                constexpr int TOT = BK * BN;
#pragma unroll
                for (int i = tid; i < TOT; i += 256) {
                    int r = i / BN, c = i % BN;
                    int n = n0 + c;
                    int ok = (fullN || n < N);
                    const float* src = Bseg + (size_t)(kk + r) * ldb + (ok ? n : 0);
                    cp4(smem_u32(&sBb[r * BPL + c]), src, ok ? 4 : 0);
                }
            }
        } else {
            constexpr int TOT = BN * 4;                // BN rows x 4 float4
#pragma unroll
            for (int i = tid; i < TOT; i += 256) {
                int r = i >> 2, c = (i & 3) * 4;
                int n = n0 + r;
                cp16(smem_u32(&sBb[r * BNS + c]), Bseg + (size_t)n * ldb + kk + c);
            }
        }
    };

    wmma::fragment<wmma::matrix_a, 16, 16, 8, wmma::precision::tf32, wmma::row_major> fa;
    wmma::fragment<wmma::accumulator, 16, 16, 8, float> fc[TN];
#pragma unroll
    for (int t = 0; t < TN; t++) wmma::fill_fragment(fc[t], 0.f);

#pragma unroll
    for (int p = 0; p < S - 1; p++) { if (p < Tper) issue(t0 + p); cp_commit(); }

    for (int t = t0; t < t0 + Tper; t++) {
        cp_wait<S - 2>();
        __syncthreads();
        int buf = (t - t0) % S;
        float* sAb = &sA[buf * 64 * AP];
        float* sBb = &sB[buf * BSTG];
#pragma unroll
        for (int ks = 0; ks < 2; ks++) {
            wmma::load_matrix_sync(fa, &sAb[wm * 16 * AP + ks * 8], AP);
#pragma unroll
            for (int i = 0; i < fa.num_elements; i++) fa.x[i] = wmma::__float_to_tf32(fa.x[i]);
#pragma unroll
            for (int tt = 0; tt < TN; tt++) {
                int ns = wn * (BN / 2) + tt * 16;
                if (!B_NK) {
                    wmma::fragment<wmma::matrix_b, 16, 16, 8, wmma::precision::tf32, wmma::row_major> fb;
                    wmma::load_matrix_sync(fb, &sBb[ks * 8 * BPL + ns], BPL);
#pragma unroll
                    for (int i = 0; i < fb.num_elements; i++) fb.x[i] = wmma::__float_to_tf32(fb.x[i]);
                    wmma::mma_sync(fc[tt], fa, fb, fc[tt]);
                } else {
                    wmma::fragment<wmma::matrix_b, 16, 16, 8, wmma::precision::tf32, wmma::col_major> fb;
                    wmma::load_matrix_sync(fb, &sBb[ns * BNS + ks * 8], BNS);
#pragma unroll
                    for (int i = 0; i < fb.num_elements; i++) fb.x[i] = wmma::__float_to_tf32(fb.x[i]);
                    wmma::mma_sync(fc[tt], fa, fb, fc[tt]);
                }
            }
        }
        __syncthreads();
        if (t + S - 1 < t0 + Tper) issue(t + S - 1);
        cp_commit();
    }

    __syncthreads();
    const bool ldc_ok = (ldc & 3) == 0;
    if (ldc_ok && fullN) {
#pragma unroll
        for (int tt = 0; tt < TN; tt++) {
            int nc = n0 + wn * (BN / 2) + tt * 16;
            wmma::store_matrix_sync(&C[(size_t)(wm * 16) * ldc + nc], fc[tt], ldc, wmma::mem_row_major);
        }
    } else {
        // stage full 64xBN tile in smem, then coalesced bounded copy
        constexpr int CP = BN + 4;
        float* sC = sA;   // spans into sB region; both dead by now
#pragma unroll
        for (int tt = 0; tt < TN; tt++) {
            int ns = wn * (BN / 2) + tt * 16;
            wmma::store_matrix_sync(&sC[(size_t)(wm * 16) * CP + ns], fc[tt], CP, wmma::mem_row_major);
        }
        __syncthreads();
        for (int i = tid; i < 64 * BN; i += 256) {
            int r = i / BN, c = i % BN;
            int n = n0 + c;
            if (n < N) C[(size_t)r * ldc + n] = sC[r * CP + c];
        }
    }
}

// ------------------------ attention scores ------------------------
__global__ void __launch_bounds__(256) k_scores(const float* __restrict__ enc) {
    int b = blockIdx.x;
    int tid = threadIdx.x, w = tid >> 5, lane = tid & 31;
    __shared__ __align__(16) float sq[2 * HH];
    for (int j = tid; j < 2 * HH; j += 256) {
        float s = 0.f;
#pragma unroll
        for (int p = 0; p < 4; p++) s += g_partqk[p * BB * 2 * HH + b * 2 * HH + j];
        sq[j] = s;
    }
    __syncthreads();

    for (int ll = w; ll < 10; ll += 8) {
        int l = blockIdx.y * 10 + ll;
        const float* e = enc + ((size_t)b * LL + l) * 2 * HH;
        float acc = 0.f;
        for (int j = lane * 4; j < 2 * HH; j += 128) {
            float4 ev = *(const float4*)(e + j);
            float4 qv = *(const float4*)(sq + j);
            acc += ev.x * qv.x + ev.y * qv.y + ev.z * qv.z + ev.w * qv.w;
        }
#pragma unroll
        for (int o = 16; o > 0; o >>= 1) acc += __shfl_xor_sync(0xffffffffu, acc, o);
        if (lane == 0) g_scores[b * LL + l] = acc * (1.f / HH);
    }
}

// ------------------------ softmax over L=50 ------------------------
__global__ void __launch_bounds__(32) k_softmax(float* __restrict__ out_attn) {
    int b = blockIdx.x, t = threadIdx.x;
    float v0 = (t < LL) ? g_scores[b * LL + t] : -1e30f;
    float v1 = (t + 32 < LL) ? g_scores[b * LL + t + 32] : -1e30f;
    float m = fmaxf(v0, v1);
#pragma unroll
    for (int o = 16; o > 0; o >>= 1) m = fmaxf(m, __shfl_xor_sync(0xffffffffu, m, o));
    float e0 = (t < LL) ? expf(v0 - m) : 0.f;
    float e1 = (t + 32 < LL) ? expf(v1 - m) : 0.f;
    float s = e0 + e1;
#pragma unroll
    for (int o = 16; o > 0; o >>= 1) s += __shfl_xor_sync(0xffffffffu, s, o);
    float inv = 1.f / s;
    if (t < LL)      { g_attn[b * LL + t] = e0 * inv;      if (out_attn) out_attn[b * LL + t] = e0 * inv; }
    if (t + 32 < LL) { g_attn[b * LL + t + 32] = e1 * inv; if (out_attn) out_attn[b * LL + t + 32] = e1 * inv; }
}

// ------------------------ weighted encoder sum ------------------------
__global__ void __launch_bounds__(256) k_wenc(const float* __restrict__ enc) {
    int b = blockIdx.x;
    int j = blockIdx.y * 256 + threadIdx.x;
    __shared__ float at[LL];
    if (threadIdx.x < LL) at[threadIdx.x] = g_attn[b * LL + threadIdx.x];
    __syncthreads();
    const float* e = enc + (size_t)b * LL * 2 * HH + j;
    float acc = 0.f;
#pragma unroll 5
    for (int l = 0; l < LL; l++) acc += at[l] * e[(size_t)l * 2 * HH];
    g_wenc[b * 2 * HH + j] = acc;
}

// ------------------------ LSTM elementwise (sums split-K parts, folds biases) ------------------------
__global__ void __launch_bounds__(256) k_lstm(const float* __restrict__ value_b,
                                              const float* __restrict__ b_x,
                                              const float* __restrict__ b_h,
                                              float* __restrict__ out_h) {
    int b = blockIdx.x;
    int h = blockIdx.y * 256 + threadIdx.x;
    float gf = b_x[h]          + b_h[h];
    float gi = b_x[HH + h]     + b_h[HH + h];
    float gc = b_x[2 * HH + h] + b_h[2 * HH + h];
    float go = b_x[3 * HH + h] + b_h[3 * HH + h];
#pragma unroll
    for (int p = 0; p < 8; p++) {
        const float* g = g_partg + (size_t)p * BB * 4 * HH + b * 4 * HH;
        gf += g[h]; gi += g[HH + h]; gc += g[2 * HH + h]; go += g[3 * HH + h];
    }
    float cp = value_b[h];
#pragma unroll
    for (int p = 0; p < 8; p++) cp += g_partc[p * BB * HH + b * HH + h];

    float f  = 1.f / (1.f + expf(-gf));
    float ig = 1.f / (1.f + expf(-gi));
    float cb = tanhf(gc);
    float o  = 1.f / (1.f + expf(-go));
    float c  = f * cp + ig * cb;
    float hn = o * tanhf(c);
    g_hnext[b * HH + h] = hn;
    if (out_h) out_h[b * HH + h] = hn;
}

// ------------------------ log-softmax: pass1 partial, pass2 apply ------------------------
#define LSM_CH 6283
__global__ void __launch_bounds__(256) k_lsm1(const float* __restrict__ logits,
                                              const float* __restrict__ out_b) {
    int b = blockIdx.x, c = blockIdx.y, tid = threadIdx.x;
    int start = c * LSM_CH, end = min(start + LSM_CH, VV);
    const float* row = logits + (size_t)b * VV;
    __shared__ float red[256];
    float m = -1e30f;
    for (int v = start + tid; v < end; v += 256) m = fmaxf(m, row[v] + out_b[v]);
    red[tid] = m; __syncthreads();
    for (int s = 128; s > 0; s >>= 1) { if (tid < s) red[tid] = fmaxf(red[tid], red[tid + s]); __syncthreads(); }
    m = red[0]; __syncthreads();
    float sum = 0.f;
    for (int v = start + tid; v < end; v += 256) sum += __expf(row[v] + out_b[v] - m);
    red[tid] = sum; __syncthreads();
    for (int s = 128; s > 0; s >>= 1) { if (tid < s) red[tid] += red[tid + s]; __syncthreads(); }
    if (tid == 0) { g_lse[(b * 8 + c) * 2] = m; g_lse[(b * 8 + c) * 2 + 1] = red[0]; }
}

__global__ void __launch_bounds__(256) k_lsm2(float* __restrict__ logits,
                                              const float* __restrict__ out_b) {
    int b = blockIdx.x, c = blockIdx.y, tid = threadIdx.x;
    float M = -1e30f;
#pragma unroll
    for (int i = 0; i < 8; i++) M = fmaxf(M, g_lse[(b * 8 + i) * 2]);
    float S = 0.f;
#pragma unroll
    for (int i = 0; i < 8; i++) S += g_lse[(b * 8 + i) * 2 + 1] * __expf(g_lse[(b * 8 + i) * 2] - M);
    float lse = M + logf(S);
    int start = c * LSM_CH, end = min(start + LSM_CH, VV);
    float* row = logits + (size_t)b * VV;
    for (int v = start + tid; v < end; v += 256) row[v] = row[v] + out_b[v] - lse;
}

// ------------------------ launch ------------------------
extern "C" void kernel_launch(void* const* d_in, const int* in_sizes, int n_in,
                              void* d_out, int out_size) {
    (void)in_sizes; (void)n_in;
    const int*   idx     = (const int*)  d_in[0];
    const float* h_prev  = (const float*)d_in[1];
    const float* enc     = (const float*)d_in[2];
    const float* emb     = (const float*)d_in[3];
    const float* w_x     = (const float*)d_in[4];
    const float* b_x     = (const float*)d_in[5];
    const float* w_h     = (const float*)d_in[6];
    const float* b_h     = (const float*)d_in[7];
    const float* key_w   = (const float*)d_in[8];
    const float* value_w = (const float*)d_in[10];
    const float* value_b = (const float*)d_in[11];
    const float* query_w = (const float*)d_in[12];
    const float* query_b = (const float*)d_in[13];
    const float* out_w   = (const float*)d_in[14];
    const float* out_b   = (const float*)d_in[15];
    // d_in[9] = key_b: dropped — softmax is shift-invariant in the constant q·key_b.

    float* out      = (float*)d_out;
    float* out_logp = out;
    float* out_h    = nullptr;
    float* out_attn = nullptr;
    long long need = (long long)BB * VV + (long long)BB * HH + (long long)BB * LL;
    if ((long long)out_size >= need) {
        out_h    = out + (size_t)BB * VV;
        out_attn = out_h + (size_t)BB * HH;
    }

    float *p_x, *p_q, *p_wenc, *p_hnext, *p_partq, *p_partqk, *p_partc, *p_partg;
    cudaGetSymbolAddress((void**)&p_x,      g_x);
    cudaGetSymbolAddress((void**)&p_q,      g_q);
    cudaGetSymbolAddress((void**)&p_wenc,   g_wenc);
    cudaGetSymbolAddress((void**)&p_hnext,  g_hnext);
    cudaGetSymbolAddress((void**)&p_partq,  g_partq);
    cudaGetSymbolAddress((void**)&p_partqk, g_partqk);
    cudaGetSymbolAddress((void**)&p_partc,  g_partc);
    cudaGetSymbolAddress((void**)&p_partg,  g_partg);

    constexpr int S = 4;
    const size_t smA   = (size_t)S * 64 * 20 * 4;
    const size_t sm_kn64  = smA + (size_t)S * 16 * 68 * 4;    // 37888
    const size_t sm_nk64  = smA + (size_t)S * 64 * 20 * 4;    // 40960
    const size_t sm_kn128 = smA + (size_t)S * 16 * 132 * 4;   // 54272

    cudaFuncSetAttribute(gemm_pipe<64, S, false>,  cudaFuncAttributeMaxDynamicSharedMemorySize, (int)sm_kn64);
    cudaFuncSetAttribute(gemm_pipe<64, S, true>,   cudaFuncAttributeMaxDynamicSharedMemorySize, (int)sm_nk64);
    cudaFuncSetAttribute(gemm_pipe<128, S, false>, cudaFuncAttributeMaxDynamicSharedMemorySize, (int)sm_kn128);

    k_gather<<<BB, 256>>>(idx, emb);

    // q partials = h_prev @ query_w  (split-K 4)
    gemm_pipe<64, S, false><<<dim3(HH / 64, 4), 256, sm_kn64>>>(
        h_prev, h_prev, HH, HH, query_w, query_w, HH, HH, p_partq, HH, HH);
    k_qbias<<<dim3(BB, 4), 256>>>(query_b);

    // qk partials = q @ key_w^T  (split-K 4)
    gemm_pipe<64, S, true><<<dim3((2 * HH) / 64, 4), 256, sm_nk64>>>(
        p_q, p_q, HH, HH, key_w, key_w, HH, HH, p_partqk, 2 * HH, 2 * HH);
    // scores (sums qk parts) -> softmax -> weighted enc sum
    k_scores<<<dim3(BB, 5), 256>>>(enc);
    k_softmax<<<BB, 32>>>(out_attn);
    k_wenc<<<dim3(BB, 8), 256>>>(enc);

    // cprev partials = wenc @ value_w  (split-K 8)
    gemm_pipe<64, S, false><<<dim3(HH / 64, 8), 256, sm_kn64>>>(
        p_wenc, p_wenc, 2 * HH, 2 * HH, value_w, value_w, HH, HH, p_partc, HH, HH);
    // gates partials = [x | h_prev] @ [w_x ; w_h]  (split-K 8)
    gemm_pipe<64, S, false><<<dim3((4 * HH) / 64, 8), 256, sm_kn64>>>(
        p_x, h_prev, HH, 2 * HH, w_x, w_h, 4 * HH, 4 * HH, p_partg, 4 * HH, 4 * HH);
    // LSTM elementwise (sums parts, folds all biases)
    k_lstm<<<dim3(BB, 4), 256>>>(value_b, b_x, b_h, out_h);

    // logits = h_next @ out_w  (no split; 393 blocks; odd-ldb cp4 path)
    gemm_pipe<128, S, false><<<dim3((VV + 127) / 128, 1), 256, sm_kn128>>>(
        p_hnext, p_hnext, HH, HH, out_w, out_w, VV, VV, out_logp, VV, VV);
    k_lsm1<<<dim3(BB, 8), 256>>>(out_logp, out_b);
    k_lsm2<<<dim3(BB, 8), 256>>>(out_logp, out_b);
}